// round 9
// baseline (speedup 1.0000x reference)
#include <cuda_runtime.h>

// CorrelationHead fused kernel, round 6: batch-pipelined persistent blocks.
// out[b,o] = b_bbox[o] + sum_{c,(i,j),(u,v) parity-matched} p1[b,c,i,j]*p2[b,c,u,v]*w[o,p,q,i,j]
//   p = (u-i)/2+10, q = (v-j)/2+10.
// Grid = 128 blocks x 4 batches each, 384 threads = 12 warps = 4 channel-groups x 3 warps.
// Double-buffered patch smem: iteration t issues LDG(t+1) -> regs, computes Gram(t) from
// buf[t&1], stores regs -> buf[(t+1)&1], one barrier per iteration. Epilogue weights
// (wpack) gathered once per block, hidden behind the batch-0 load.
// Gram math identical to round 5 (parity classes over the 7x7 grid, 4x4 register tiles).

#define NB       512
#define NC       128
#define HW       49
#define FEAT     21609
#define NTHREADS 384
#define NBLK     128
#define BPB      4                              // batches per block
#define TF4      1568                           // float4 per tensor per batch (128*49/4)
#define GF4      392                            // float4 per tensor per channel-group
#define BUF_FLOATS (2 * NC * HW)                // 12544 per buffer (s1+s2)
#define WP4      1088                           // 64 rows x 17 float4
#define SMEM_FLOATS (2 * BUF_FLOATS + 4 * WP4)  // 29440
#define SMEM_BYTES  (SMEM_FLOATS * 4)           // 117760

__device__ __forceinline__ void load_batch(float4 v[9],
    const float4* __restrict__ p14, const float4* __restrict__ p24,
    int b, int grp, int g96)
{
    const float4* t1 = p14 + (size_t)b * TF4 + grp * GF4;
    const float4* t2 = p24 + (size_t)b * TF4 + grp * GF4;
#pragma unroll
    for (int f = 0; f < 8; f++) {
        int idx = g96 + f * 96;                 // 0..767 of 784
        v[f] = (idx < GF4) ? t1[idx] : t2[idx - GF4];
    }
    if (g96 < 16) v[8] = t2[g96 + 768 - GF4];
}

__device__ __forceinline__ void store_batch(const float4 v[9],
    float4* buf4, int grp, int g96)
{
#pragma unroll
    for (int f = 0; f < 8; f++) {
        int idx = g96 + f * 96;
        int dst = (idx < GF4) ? (grp * GF4 + idx)
                              : (TF4 + grp * GF4 + idx - GF4);
        buf4[dst] = v[f];
    }
    if (g96 < 16) buf4[TF4 + grp * GF4 + g96 + 768 - GF4] = v[8];
}

__global__ __launch_bounds__(NTHREADS, 1) void corr_head_kernel(
    const float* __restrict__ p1, const float* __restrict__ p2,
    const float* __restrict__ w, const float* __restrict__ bb,
    float* __restrict__ out)
{
    extern __shared__ float sm[];
    float* wp = sm + 2 * BUF_FLOATS;            // wpack: 1088 float4
    __shared__ float sred[2][12][4];

    const int tid = threadIdx.x;
    const int bid = blockIdx.x;
    const int warp = tid >> 5, lane = tid & 31;
    const int grp = warp / 3;                   // channel group (32 ch)
    const int wg  = warp - 3 * grp;
    const int h   = lane >> 4;                  // channel half (16 ch)
    const int l16 = lane & 15;
    const int g96 = tid - grp * 96;             // group-local id (warps consecutive)

    // ---- per-lane tile assignment (identical to round 5) ----
    int cls, tx, ty, pidx;
    if (wg == 0) {
        cls = 0; tx = l16 >> 2; ty = l16 & 3; pidx = l16;
    } else {
        int v = (wg - 1) * 16 + l16;
        if (v < 27) { cls = 1 + v / 9; int u = v - 9 * (v / 9); tx = u / 3; ty = u - 3 * (u / 3); }
        else        { cls = 1; tx = 3; ty = 3; }    // dummy -> all-zero weights
        pidx = tx * 3 + ty;
    }
    int aB, bB, st;
    if (cls == 0)      { aB = 2 * tx;      bB = 2 * ty;      st = 14; }
    else if (cls == 1) { aB = 2 * tx + 1;  bB = 2 * ty + 1;  st = 14; }
    else if (cls == 2) { aB = 14 * tx + 7; bB = 14 * ty + 7; st = 2;  }
    else               { aB = 8 + 2 * tx;  bB = 8 + 2 * ty;  st = 14; }
    const int cb = (grp * 32 + h * 16) * HW;

    const float4* p14 = (const float4*)p1;
    const float4* p24 = (const float4*)p2;
    const int b0 = bid * BPB;

    // ---- prologue: issue batch-0 patch loads, then wpack gather (overlapped) ----
    float4 v[9];
    load_batch(v, p14, p24, b0, grp, g96);

#pragma unroll
    for (int e = 0; e < 3; e++) {
        int cell = tid + e * NTHREADS;
        if (cell < 1024) {
            int c2  = cell >> 8;
            int p   = (cell >> 4) & 15;
            int k   = cell & 15;
            int xa = k >> 2, yb = k & 3;
            int ttx, tty, i, j, pp, qq;
            bool valid;
            if (c2 == 0) {
                ttx = p >> 2; tty = p & 3;
                i = 2 * xa; j = 2 * ttx; pp = yb - xa + 10; qq = tty - ttx + 10;
                valid = true;
            } else {
                ttx = p / 3; tty = p - 3 * (p / 3);
                valid = (p < 9) && (c2 != 3 || (xa < 3 && yb < 3));
                if (c2 == 1)      { i = 2 * xa;      j = 2 * ttx + 1; pp = yb - xa + 10;  qq = tty - ttx + 10; }
                else if (c2 == 2) { i = 2 * ttx + 1; j = 2 * xa;      pp = tty - ttx + 10; qq = yb - xa + 10; }
                else              { i = 2 * xa + 1;  j = 2 * ttx + 1; pp = yb - xa + 10;  qq = tty - ttx + 10; }
            }
            float4 wv = make_float4(0.f, 0.f, 0.f, 0.f);
            if (valid) {
                int widx = ((pp * 21 + qq) * 7 + i) * 7 + j;
                wv.x = __ldg(&w[0 * FEAT + widx]);
                wv.y = __ldg(&w[1 * FEAT + widx]);
                wv.z = __ldg(&w[2 * FEAT + widx]);
                wv.w = __ldg(&w[3 * FEAT + widx]);
            }
            ((float4*)wp)[(cell >> 4) * 17 + k] = wv;
        }
    }

    // guard: dummy-tile one-float overflow of bufA.s2 lands at bufB[0] (read at t=0)
    if (tid == 0) sm[BUF_FLOATS] = 0.f;

    store_batch(v, (float4*)sm, grp, g96);      // batch 0 -> buffer 0
    __syncthreads();

    // ---- batch loop, double-buffered ----
#pragma unroll
    for (int t = 0; t < BPB; t++) {
        const int b = b0 + t;

        if (t < BPB - 1)
            load_batch(v, p14, p24, b + 1, grp, g96);   // issue early, consume late

        const float* base = sm + (t & 1) * BUF_FLOATS;
        const float* a0p = base + cb + aB;
        const float* a1p = a0p + st;
        const float* a2p = a0p + 2 * st;
        const float* a3p = a0p + 3 * st;
        const float* b0p = base + NC * HW + cb + bB;
        const float* b1p = b0p + st;
        const float* b2p = b0p + 2 * st;
        const float* b3p = b0p + 3 * st;

        float g[16];
#pragma unroll
        for (int k = 0; k < 16; k++) g[k] = 0.f;
#pragma unroll 8
        for (int c = 0; c < 16; c++) {
            const int o = c * HW;
            float a0 = a0p[o], a1 = a1p[o], a2 = a2p[o], a3 = a3p[o];
            float x0 = b0p[o], x1 = b1p[o], x2 = b2p[o], x3 = b3p[o];
            g[0]  += a0 * x0; g[1]  += a0 * x1; g[2]  += a0 * x2; g[3]  += a0 * x3;
            g[4]  += a1 * x0; g[5]  += a1 * x1; g[6]  += a1 * x2; g[7]  += a1 * x3;
            g[8]  += a2 * x0; g[9]  += a2 * x1; g[10] += a2 * x2; g[11] += a2 * x3;
            g[12] += a3 * x0; g[13] += a3 * x1; g[14] += a3 * x2; g[15] += a3 * x3;
        }

        if (t < BPB - 1)
            store_batch(v, (float4*)(sm + ((t + 1) & 1) * BUF_FLOATS), grp, g96);

        // merge channel halves
#pragma unroll
        for (int k = 0; k < 16; k++)
            g[k] += __shfl_down_sync(0xffffffffu, g[k], 16);

        // contract with pre-gathered weights
        float lacc[4] = {0.f, 0.f, 0.f, 0.f};
        if (h == 0) {
            const float4* wr = ((const float4*)wp) + (cls * 16 + pidx) * 17;
#pragma unroll
            for (int k = 0; k < 16; k++) {
                float4 ww = wr[k];
                float gv = g[k];
                lacc[0] += gv * ww.x; lacc[1] += gv * ww.y;
                lacc[2] += gv * ww.z; lacc[3] += gv * ww.w;
            }
        }
#pragma unroll
        for (int off = 16; off; off >>= 1) {
#pragma unroll
            for (int o = 0; o < 4; o++)
                lacc[o] += __shfl_down_sync(0xffffffffu, lacc[o], off);
        }
        if (lane == 0) {
#pragma unroll
            for (int o = 0; o < 4; o++) sred[t & 1][warp][o] = lacc[o];
        }
        __syncthreads();     // publishes sred(t) AND buf(t+1) stores

        if (tid < 4) {
            float s = bb[tid];
#pragma unroll
            for (int wi = 0; wi < 12; wi++) s += sred[t & 1][wi][tid];
            out[b * 4 + tid] = s;
        }
    }
}

extern "C" void kernel_launch(void* const* d_in, const int* in_sizes, int n_in,
                              void* d_out, int out_size) {
    const float* p1 = (const float*)d_in[0];   // patch1 [512,128,7,7]
    const float* p2 = (const float*)d_in[1];   // patch2 [512,128,7,7]
    const float* w  = (const float*)d_in[2];   // w_bbox [4,21609]
    const float* bb = (const float*)d_in[3];   // b_bbox [4]
    float* out = (float*)d_out;                // [512,4] float32

    static int smem_set = 0;
    if (!smem_set) {
        cudaFuncSetAttribute(corr_head_kernel,
                             cudaFuncAttributeMaxDynamicSharedMemorySize, SMEM_BYTES);
        smem_set = 1;
    }
    corr_head_kernel<<<NBLK, NTHREADS, SMEM_BYTES>>>(p1, p2, w, bb, out);
}

// round 10
// speedup vs baseline: 1.3633x; 1.3633x over previous
#include <cuda_runtime.h>

// CorrelationHead fused kernel, round 7: R5 base + intra-block channel-chunk pipeline.
// out[b,o] = b_bbox[o] + sum_{c,(i,j),(u,v) parity-matched} p1[b,c,i,j]*p2[b,c,u,v]*w[o,p,q,i,j]
//   p = (u-i)/2+10, q = (v-j)/2+10.
// 512 blocks (1 batch each), 384 threads = 12 warps = 4 channel-groups x 3 warps.
//   wg=0: class 0 (16 tiles); wg=1,2: classes 1,2,3 (27 tiles) packed; x2 channel halves.
// Patches staged in two 64-channel chunks: chunk0 copied directly (its DRAM latency
// overlaps the wpack weight gather), chunk1's LDGs issued before chunk0's Gram compute
// and stored between compute halves. Epilogue: every lane contracts its half-Gram with
// the pre-gathered wpack row (broadcast LDS), one 5-level shfl tree sums everything.

#define NB       512
#define NC       128
#define HW       49
#define FEAT     21609
#define NTHREADS 384
#define TF4      1568                           // float4 per tensor per batch
#define F4C      784                            // float4 per tensor per chunk (64 ch)
#define CHUNK_FLOATS (2 * 64 * HW)              // 6272 (s1 + s2 of one chunk)
#define WP4      1088                           // 64 rows x 17 float4
#define SMEM_FLOATS (2 * CHUNK_FLOATS + 4 * WP4)   // 16896
#define SMEM_BYTES  (SMEM_FLOATS * 4)              // 67584

// Gram over 4 channels (c0..c0+3) of an 8-channel slice, natural layout.
__device__ __forceinline__ void gram4(float g[16], const float* __restrict__ ap,
                                      const float* __restrict__ bp, int st, int c0)
{
#pragma unroll
    for (int c = 0; c < 4; c++) {
        const int o = (c0 + c) * HW;
        float a0 = ap[o], a1 = ap[o + st], a2 = ap[o + 2 * st], a3 = ap[o + 3 * st];
        float x0 = bp[o], x1 = bp[o + st], x2 = bp[o + 2 * st], x3 = bp[o + 3 * st];
        g[0]  += a0 * x0; g[1]  += a0 * x1; g[2]  += a0 * x2; g[3]  += a0 * x3;
        g[4]  += a1 * x0; g[5]  += a1 * x1; g[6]  += a1 * x2; g[7]  += a1 * x3;
        g[8]  += a2 * x0; g[9]  += a2 * x1; g[10] += a2 * x2; g[11] += a2 * x3;
        g[12] += a3 * x0; g[13] += a3 * x1; g[14] += a3 * x2; g[15] += a3 * x3;
    }
}

__global__ __launch_bounds__(NTHREADS, 3) void corr_head_kernel(
    const float* __restrict__ p1, const float* __restrict__ p2,
    const float* __restrict__ w, const float* __restrict__ bb,
    float* __restrict__ out)
{
    extern __shared__ float sm[];
    float* chunk0 = sm;                        // [64*49 s1][64*49 s2]
    float* chunk1 = sm + CHUNK_FLOATS;
    float* wp     = sm + 2 * CHUNK_FLOATS;     // wpack: 1088 float4
    __shared__ float sred[12][4];

    const int tid = threadIdx.x;
    const int b = blockIdx.x;
    const int warp = tid >> 5, lane = tid & 31;
    const int grp = warp / 3;                  // channel group
    const int wg  = warp - 3 * grp;
    const int h   = lane >> 4;                 // channel half
    const int l16 = lane & 15;

    // ---- per-lane tile assignment ----
    int cls, tx, ty, pidx;
    if (wg == 0) {
        cls = 0; tx = l16 >> 2; ty = l16 & 3; pidx = l16;
    } else {
        int v = (wg - 1) * 16 + l16;
        if (v < 27) { cls = 1 + v / 9; int u = v - 9 * (v / 9); tx = u / 3; ty = u - 3 * (u / 3); }
        else        { cls = 1; tx = 3; ty = 3; }    // dummy -> all-zero weights
        pidx = tx * 3 + ty;
    }
    int aB, bB, st;
    if (cls == 0)      { aB = 2 * tx;      bB = 2 * ty;      st = 14; }
    else if (cls == 1) { aB = 2 * tx + 1;  bB = 2 * ty + 1;  st = 14; }
    else if (cls == 2) { aB = 14 * tx + 7; bB = 14 * ty + 7; st = 2;  }
    else               { aB = 8 + 2 * tx;  bB = 8 + 2 * ty;  st = 14; }
    const int slice = (16 * grp + 8 * h) * HW;     // 8-channel slice within a chunk

    const float4* t1 = (const float4*)p1 + (size_t)b * TF4;
    const float4* t2 = (const float4*)p2 + (size_t)b * TF4;
    const bool tl = tid < 16;

    // ---- phase A: wpack gather (LDGs overlap chunk0 DRAM), chunk0 direct copy ----
    float4* c04 = (float4*)chunk0;
    c04[tid] = t1[tid];
    c04[tid + 384] = t1[tid + 384];
    if (tl) c04[tid + 768] = t1[tid + 768];
    c04[F4C + tid] = t2[tid];
    c04[F4C + tid + 384] = t2[tid + 384];
    if (tl) c04[F4C + tid + 768] = t2[tid + 768];
    if (tid < 64) chunk1[tid] = 0.f;           // finite-guard for dummy-lane overreads

#pragma unroll
    for (int e = 0; e < 3; e++) {
        int cell = tid + e * NTHREADS;
        if (cell < 1024) {
            int c2  = cell >> 8;
            int p   = (cell >> 4) & 15;
            int k   = cell & 15;
            int xa = k >> 2, yb = k & 3;
            int ttx, tty, i, j, pp, qq;
            bool valid;
            if (c2 == 0) {
                ttx = p >> 2; tty = p & 3;
                i = 2 * xa; j = 2 * ttx; pp = yb - xa + 10; qq = tty - ttx + 10;
                valid = true;
            } else {
                ttx = p / 3; tty = p - 3 * (p / 3);
                valid = (p < 9) && (c2 != 3 || (xa < 3 && yb < 3));
                if (c2 == 1)      { i = 2 * xa;      j = 2 * ttx + 1; pp = yb - xa + 10;  qq = tty - ttx + 10; }
                else if (c2 == 2) { i = 2 * ttx + 1; j = 2 * xa;      pp = tty - ttx + 10; qq = yb - xa + 10; }
                else              { i = 2 * xa + 1;  j = 2 * ttx + 1; pp = yb - xa + 10;  qq = tty - ttx + 10; }
            }
            float4 wv = make_float4(0.f, 0.f, 0.f, 0.f);
            if (valid) {
                int widx = ((pp * 21 + qq) * 7 + i) * 7 + j;
                wv.x = __ldg(&w[0 * FEAT + widx]);
                wv.y = __ldg(&w[1 * FEAT + widx]);
                wv.z = __ldg(&w[2 * FEAT + widx]);
                wv.w = __ldg(&w[3 * FEAT + widx]);
            }
            ((float4*)wp)[(cell >> 4) * 17 + k] = wv;
        }
    }
    __syncthreads();

    // ---- phase B: LDG chunk1 in flight while computing Gram over chunk0 ----
    const float4* t1b = t1 + F4C;
    const float4* t2b = t2 + F4C;
    float4* c14 = (float4*)chunk1;

    float4 u0 = t1b[tid], u1 = t1b[tid + 384], u2;
    if (tl) u2 = t1b[tid + 768];

    float g[16];
#pragma unroll
    for (int k = 0; k < 16; k++) g[k] = 0.f;

    const float* a0 = chunk0 + slice + aB;
    const float* b0 = chunk0 + CHUNK_FLOATS / 2 + slice + bB;
    gram4(g, a0, b0, st, 0);

    c14[tid] = u0;
    c14[tid + 384] = u1;
    if (tl) c14[tid + 768] = u2;
    float4 w0 = t2b[tid], w1 = t2b[tid + 384], w2;
    if (tl) w2 = t2b[tid + 768];

    gram4(g, a0, b0, st, 4);

    c14[F4C + tid] = w0;
    c14[F4C + tid + 384] = w1;
    if (tl) c14[F4C + tid + 768] = w2;
    __syncthreads();

    // ---- phase C: Gram over chunk1 ----
    const float* a1 = chunk1 + slice + aB;
    const float* b1 = chunk1 + CHUNK_FLOATS / 2 + slice + bB;
    gram4(g, a1, b1, st, 0);
    gram4(g, a1, b1, st, 4);

    // ---- contract with pre-gathered weights (all 32 lanes; wpack row broadcast) ----
    float lacc[4] = {0.f, 0.f, 0.f, 0.f};
    {
        const float4* wr = ((const float4*)wp) + (cls * 16 + pidx) * 17;
#pragma unroll
        for (int k = 0; k < 16; k++) {
            float4 ww = wr[k];
            float gv = g[k];
            lacc[0] += gv * ww.x; lacc[1] += gv * ww.y;
            lacc[2] += gv * ww.z; lacc[3] += gv * ww.w;
        }
    }

    // ---- deterministic reduction + bias ----
#pragma unroll
    for (int off = 16; off; off >>= 1) {
#pragma unroll
        for (int o = 0; o < 4; o++)
            lacc[o] += __shfl_down_sync(0xffffffffu, lacc[o], off);
    }
    if (lane == 0) {
#pragma unroll
        for (int o = 0; o < 4; o++) sred[warp][o] = lacc[o];
    }
    __syncthreads();
    if (tid < 4) {
        float s = bb[tid];
#pragma unroll
        for (int wi = 0; wi < 12; wi++) s += sred[wi][tid];
        out[b * 4 + tid] = s;
    }
}

extern "C" void kernel_launch(void* const* d_in, const int* in_sizes, int n_in,
                              void* d_out, int out_size) {
    const float* p1 = (const float*)d_in[0];   // patch1 [512,128,7,7]
    const float* p2 = (const float*)d_in[1];   // patch2 [512,128,7,7]
    const float* w  = (const float*)d_in[2];   // w_bbox [4,21609]
    const float* bb = (const float*)d_in[3];   // b_bbox [4]
    float* out = (float*)d_out;                // [512,4] float32

    static int smem_set = 0;
    if (!smem_set) {
        cudaFuncSetAttribute(corr_head_kernel,
                             cudaFuncAttributeMaxDynamicSharedMemorySize, SMEM_BYTES);
        smem_set = 1;
    }
    corr_head_kernel<<<NB, NTHREADS, SMEM_BYTES>>>(p1, p2, w, bb, out);
}

// round 12
// speedup vs baseline: 1.5522x; 1.1385x over previous
#include <cuda_runtime.h>

// CorrelationHead fused kernel, round 8: R5 structure + packed f32x2 FMA (FFMA2).
// out[b,o] = b_bbox[o] + sum_{c,(i,j),(u,v) parity-matched} p1[b,c,i,j]*p2[b,c,u,v]*w[o,p,q,i,j]
//   p = (u-i)/2+10, q = (v-j)/2+10.
// One block per batch, 384 threads = 12 warps = 4 channel-groups x 3 warps.
//   wg=0: class 0 (16 tiles); wg=1,2: classes 1,2,3 (27 tiles packed); x2 channel halves.
// Gram: 4x4 register tile per thread over 16 channels, natural s[c][49] smem layout,
// accumulated in 8 packed f32x2 registers via fma.rn.f32x2 (halves fma-pipe issue).
// Epilogue weights pre-gathered into smem wpack (zeros for invalid/dummy entries).

#define NB       512
#define NC       128
#define HW       49
#define FEAT     21609
#define NTHREADS 384
#define SROW     (NC * HW + 8)                 // 6280 floats per tensor (8 zero pad)
#define WP4      1088                          // 64 rows x 17 float4
#define SMEM_FLOATS (2 * SROW + 4 * WP4)       // 16912
#define SMEM_BYTES  (SMEM_FLOATS * 4)          // 67648

typedef unsigned long long u64;

__device__ __forceinline__ u64 pk2(float x, float y) {
    u64 r; asm("mov.b64 %0, {%1, %2};" : "=l"(r) : "f"(x), "f"(y)); return r;
}
__device__ __forceinline__ void fma2(u64& d, u64 a, u64 b) {
    asm("fma.rn.f32x2 %0, %1, %2, %0;" : "+l"(d) : "l"(a), "l"(b));
}
__device__ __forceinline__ void add2(u64& d, u64 a) {
    asm("add.rn.f32x2 %0, %0, %1;" : "+l"(d) : "l"(a));
}
__device__ __forceinline__ float2 up2(u64 v) {
    float2 f; asm("mov.b64 {%0, %1}, %2;" : "=f"(f.x), "=f"(f.y) : "l"(v)); return f;
}

__global__ __launch_bounds__(NTHREADS, 3) void corr_head_kernel(
    const float* __restrict__ p1, const float* __restrict__ p2,
    const float* __restrict__ w, const float* __restrict__ bb,
    float* __restrict__ out)
{
    extern __shared__ float sm[];
    float* s1 = sm;                      // [128*49 + 8]
    float* s2 = sm + SROW;
    float* wp = sm + 2 * SROW;           // [1088 float4]
    __shared__ float sred[12][4];

    const int tid = threadIdx.x;
    const int b = blockIdx.x;

    // ---- linear copy: gmem -> natural smem layout ----
    const float4* p14 = (const float4*)(p1 + (size_t)b * NC * HW);
    const float4* p24 = (const float4*)(p2 + (size_t)b * NC * HW);
    float4* s14 = (float4*)s1;
    float4* s24 = (float4*)s2;
#pragma unroll
    for (int it = 0; it < 5; it++) {
        int idx4 = tid + it * NTHREADS;
        if (idx4 < NC * HW / 4) {        // 1568
            s14[idx4] = p14[idx4];
            s24[idx4] = p24[idx4];
        }
    }
    if (tid < 8) { s1[NC * HW + tid] = 0.f; s2[NC * HW + tid] = 0.f; }

    // ---- pre-gather epilogue weights into wpack (1024 cells, zeros for invalid) ----
#pragma unroll
    for (int e = 0; e < 3; e++) {
        int cell = tid + e * NTHREADS;
        if (cell < 1024) {
            int cls = cell >> 8;
            int p   = (cell >> 4) & 15;
            int k   = cell & 15;
            int xa = k >> 2, yb = k & 3;
            int tx, ty, i, j, pp, qq;
            bool valid;
            if (cls == 0) {
                tx = p >> 2; ty = p & 3;
                i = 2 * xa; j = 2 * tx; pp = yb - xa + 10; qq = ty - tx + 10;
                valid = true;
            } else {
                tx = p / 3; ty = p - 3 * (p / 3);
                valid = (p < 9) && (cls != 3 || (xa < 3 && yb < 3));
                if (cls == 1)      { i = 2 * xa;     j = 2 * tx + 1; pp = yb - xa + 10; qq = ty - tx + 10; }
                else if (cls == 2) { i = 2 * tx + 1; j = 2 * xa;     pp = ty - tx + 10; qq = yb - xa + 10; }
                else               { i = 2 * xa + 1; j = 2 * tx + 1; pp = yb - xa + 10; qq = ty - tx + 10; }
            }
            float4 wv = make_float4(0.f, 0.f, 0.f, 0.f);
            if (valid) {
                int widx = ((pp * 21 + qq) * 7 + i) * 7 + j;
                wv.x = __ldg(&w[0 * FEAT + widx]);
                wv.y = __ldg(&w[1 * FEAT + widx]);
                wv.z = __ldg(&w[2 * FEAT + widx]);
                wv.w = __ldg(&w[3 * FEAT + widx]);
            }
            ((float4*)wp)[(cell >> 4) * 17 + k] = wv;
        }
    }
    __syncthreads();

    // ---- per-lane tile assignment ----
    const int warp = tid >> 5, lane = tid & 31;
    const int grp = warp / 3;            // channel group (32 ch)
    const int wg  = warp - 3 * grp;      // 0: cls0, 1/2: cls1-3 packed
    const int h   = lane >> 4;           // channel half (16 ch)
    const int l16 = lane & 15;

    int cls, tx, ty, pidx;
    if (wg == 0) {
        cls = 0; tx = l16 >> 2; ty = l16 & 3; pidx = l16;
    } else {
        int v = (wg - 1) * 16 + l16;     // 0..31, valid < 27
        if (v < 27) { cls = 1 + v / 9; int u = v - 9 * (v / 9); tx = u / 3; ty = u - 3 * (u / 3); }
        else        { cls = 1; tx = 3; ty = 3; }   // dummy: p=12 -> all-zero weights
        pidx = tx * 3 + ty;
    }
    int aB, bB, st;
    if (cls == 0)      { aB = 2 * tx;        bB = 2 * ty;        st = 14; }
    else if (cls == 1) { aB = 2 * tx + 1;    bB = 2 * ty + 1;    st = 14; }
    else if (cls == 2) { aB = 14 * tx + 7;   bB = 14 * ty + 7;   st = 2;  }
    else               { aB = 8 + 2 * tx;    bB = 8 + 2 * ty;    st = 14; }

    const int cb = (grp * 32 + h * 16) * HW;
    const float* a0p = s1 + cb + aB;
    const float* a1p = a0p + st;
    const float* a2p = a0p + 2 * st;
    const float* a3p = a0p + 3 * st;
    const float* b0p = s2 + cb + bB;
    const float* b1p = b0p + st;
    const float* b2p = b0p + 2 * st;
    const float* b3p = b0p + 3 * st;

    // ---- Gram over 16 channels: 8 LDS + 8 FFMA2 per channel ----
    // g2[2m]   = { g[4m+0], g[4m+1] }  (a_m x {b0,b1})
    // g2[2m+1] = { g[4m+2], g[4m+3] }  (a_m x {b2,b3})
    u64 g2[8];
#pragma unroll
    for (int k = 0; k < 8; k++) g2[k] = pk2(0.f, 0.f);
#pragma unroll 8
    for (int c = 0; c < 16; c++) {
        const int o = c * HW;
        float a0 = a0p[o], a1 = a1p[o], a2 = a2p[o], a3 = a3p[o];
        float b0 = b0p[o], b1 = b1p[o], b2 = b2p[o], b3 = b3p[o];
        u64 bp01 = pk2(b0, b1), bp23 = pk2(b2, b3);
        u64 aa;
        aa = pk2(a0, a0); fma2(g2[0], aa, bp01); fma2(g2[1], aa, bp23);
        aa = pk2(a1, a1); fma2(g2[2], aa, bp01); fma2(g2[3], aa, bp23);
        aa = pk2(a2, a2); fma2(g2[4], aa, bp01); fma2(g2[5], aa, bp23);
        aa = pk2(a3, a3); fma2(g2[6], aa, bp01); fma2(g2[7], aa, bp23);
    }

    // ---- merge channel halves (lane <- lane+16: same tile by construction) ----
#pragma unroll
    for (int k = 0; k < 8; k++) {
        u64 oth = __shfl_down_sync(0xffffffffu, g2[k], 16);
        add2(g2[k], oth);
    }

    // ---- contract with pre-gathered weights (packed over output pairs) ----
    u64 lacc01 = pk2(0.f, 0.f), lacc23 = pk2(0.f, 0.f);
    if (h == 0) {
        const float4* wr = ((const float4*)wp) + (cls * 16 + pidx) * 17;
#pragma unroll
        for (int t = 0; t < 8; t++) {
            float2 gp = up2(g2[t]);
            float4 wA = wr[2 * t];
            float4 wB = wr[2 * t + 1];
            u64 gg;
            gg = pk2(gp.x, gp.x);
            fma2(lacc01, gg, pk2(wA.x, wA.y));
            fma2(lacc23, gg, pk2(wA.z, wA.w));
            gg = pk2(gp.y, gp.y);
            fma2(lacc01, gg, pk2(wB.x, wB.y));
            fma2(lacc23, gg, pk2(wB.z, wB.w));
        }
    }

    // ---- deterministic block reduction + bias ----
#pragma unroll
    for (int off = 16; off; off >>= 1) {
        u64 o01 = __shfl_down_sync(0xffffffffu, lacc01, off);
        u64 o23 = __shfl_down_sync(0xffffffffu, lacc23, off);
        add2(lacc01, o01);
        add2(lacc23, o23);
    }
    if (lane == 0) {
        float2 r01 = up2(lacc01), r23 = up2(lacc23);
        sred[warp][0] = r01.x; sred[warp][1] = r01.y;
        sred[warp][2] = r23.x; sred[warp][3] = r23.y;
    }
    __syncthreads();
    if (tid < 4) {
        float s = bb[tid];
#pragma unroll
        for (int wi = 0; wi < 12; wi++) s += sred[wi][tid];
        out[b * 4 + tid] = s;
    }
}

extern "C" void kernel_launch(void* const* d_in, const int* in_sizes, int n_in,
                              void* d_out, int out_size) {
    const float* p1 = (const float*)d_in[0];   // patch1 [512,128,7,7]
    const float* p2 = (const float*)d_in[1];   // patch2 [512,128,7,7]
    const float* w  = (const float*)d_in[2];   // w_bbox [4,21609]
    const float* bb = (const float*)d_in[3];   // b_bbox [4]
    float* out = (float*)d_out;                // [512,4] float32

    static int smem_set = 0;
    if (!smem_set) {
        cudaFuncSetAttribute(corr_head_kernel,
                             cudaFuncAttributeMaxDynamicSharedMemorySize, SMEM_BYTES);
        smem_set = 1;
    }
    corr_head_kernel<<<NB, NTHREADS, SMEM_BYTES>>>(p1, p2, w, bb, out);
}